// round 5
// baseline (speedup 1.0000x reference)
#include <cuda_runtime.h>
#include <cstdio>

// ContinuousWaveletTransform: out[b,i,n] = sum_{k=0}^{15} w[k]*signal[b, n - wl_i + k]
// w[k] = exp(-0.5 k^2) * exp(j*(2pi/6)*k), norm = max|w| = 1 (at k=0).
// Gaussian envelope < 2.3e-11 past k=7 -> 16 taps reproduce the full reference
// convolution (up to 2048 taps) to ~1e-11 relative. Scales differ only by shift wl_i.
//
// Output-mode adaptive: the harness's out_size tells us whether the output buffer
// holds real-part floats (524288) or interleaved complex floats (1048576).

#define CWT_NSCALES 32
#define CWT_L       4096
#define CWT_B       4
#define CWT_K       16
#define CWT_TPB     256

// wl_i = even(max(8, min(L/2, int(64 * linspace(1,64,32)[i]))))
__constant__ int c_wl[CWT_NSCALES] = {
      64,  194,  324,  454,  584,  714,  844,  974,
    1104, 1234, 1364, 1494, 1624, 1754, 1884, 2014,
    2048, 2048, 2048, 2048, 2048, 2048, 2048, 2048,
    2048, 2048, 2048, 2048, 2048, 2048, 2048, 2048
};

// mode 0: out[oidx] = re               (float32 real-part output, out_size floats)
// mode 1: out[2*oidx]=re, out[2*oidx+1]=im  (interleaved complex floats)
__global__ void __launch_bounds__(CWT_TPB)
cwt81003_kernel(const float* __restrict__ sig, int sig_elems,
                float* __restrict__ out, long out_floats, int mode)
{
    const int tid = threadIdx.x;
    const int i   = blockIdx.y;   // scale
    const int b   = blockIdx.z;   // batch
    const int n0  = blockIdx.x * CWT_TPB;
    const int n   = n0 + tid;

    const int wl = c_wl[i];

    __shared__ float s_tile[CWT_TPB + CWT_K];
    __shared__ float s_wr[CWT_K];
    __shared__ float s_wi[CWT_K];

    // Taps (reference fp32 math: env=exp(-0.5 t^2), ph=float32(2pi/6)*t, nrm=1)
    if (tid < CWT_K) {
        float t   = (float)tid;
        float env = expf(-0.5f * t * t);
        float ph  = (float)(2.0 * 3.14159265358979323846 / 6.0) * t;
        s_wr[tid] = env * cosf(ph);
        s_wi[tid] = env * sinf(ph);
    }

    // Cooperative tile: signal[b, base .. base+TPB+K), zero outside [0, L)
    const int base     = n0 - wl;
    const int sig_base = b * CWT_L;
    for (int j = tid; j < CWT_TPB + CWT_K; j += CWT_TPB) {
        int g  = base + j;
        int gi = sig_base + g;
        float v = 0.0f;
        if (g >= 0 && g < CWT_L && gi < sig_elems) v = sig[gi];
        s_tile[j] = v;
    }
    __syncthreads();

    float re = 0.0f, im = 0.0f;
    #pragma unroll
    for (int k = 0; k < CWT_K; k++) {
        float x = s_tile[tid + k];
        re = fmaf(s_wr[k], x, re);
        im = fmaf(s_wi[k], x, im);
    }

    const long oidx = ((long)(b * CWT_NSCALES + i)) * CWT_L + n;
    if (mode == 0) {
        if (oidx < out_floats) out[oidx] = re;
    } else {
        long fre = 2 * oidx, fim = 2 * oidx + 1;
        if (fre < out_floats) out[fre] = re;
        if (fim < out_floats) out[fim] = im;
    }
}

extern "C" void kernel_launch(void* const* d_in, const int* in_sizes, int n_in,
                              void* d_out, int out_size)
{
    // Diagnostics: shows up in the harness error log on any failure.
    fprintf(stderr, "DIAG kernel_launch: n_in=%d out_size=%d in_sizes[0]=%d\n",
            n_in, out_size, (n_in > 0 ? in_sizes[0] : -1));

    const float* sig = (const float*)d_in[0];
    float* out = (float*)d_out;

    const long logical = (long)CWT_B * CWT_NSCALES * CWT_L;  // 524288 outputs

    int  mode;
    long out_floats;
    if ((long)out_size == logical) {           // float32 real-part output buffer
        mode = 0;  out_floats = logical;
    } else if ((long)out_size == 2 * logical) {// interleaved re/im floats
        mode = 1;  out_floats = 2 * logical;
    } else {                                   // unknown: clamp hard, real-only
        mode = 0;  out_floats = (long)out_size;
    }

    dim3 grid(CWT_L / CWT_TPB, CWT_NSCALES, CWT_B);
    cwt81003_kernel<<<grid, CWT_TPB>>>(sig, in_sizes[0], out, out_floats, mode);
}

// round 6
// speedup vs baseline: 1.2977x; 1.2977x over previous
#include <cuda_runtime.h>

// CWT, exact structure: out[b,i,n] = Re{ sum_k w[k] * signal[b, n - wl_i + k] }
// w[k] = exp(-0.5 k^2) * exp(j*2pi*k/6), nrm = 1. Envelope < 1.3e-14 past k=7,
// so K=8 taps are exact to fp32. Harness output buffer = float32 real part
// (out_size == 524288 confirmed in R5). Taps are hardcoded constants.

#define CWT_NSCALES 32
#define CWT_L       4096
#define CWT_B       4
#define CWT_K       8
#define CWT_V       8      // outputs per thread
#define CWT_TPB     256

__constant__ int c_wl[CWT_NSCALES] = {
      64,  194,  324,  454,  584,  714,  844,  974,
    1104, 1234, 1364, 1494, 1624, 1754, 1884, 2014,
    2048, 2048, 2048, 2048, 2048, 2048, 2048, 2048,
    2048, 2048, 2048, 2048, 2048, 2048, 2048, 2048
};

// w_re[k] = exp(-0.5 k^2) * cos(2 pi k / 6)
__device__ __constant__ float c_wr[CWT_K] = {
    1.0f,                    0.3032653298563167f,  -0.06766764161830635f,
   -0.011108996538242306f,  -1.6773131395125593e-4f, 1.8633265860393355e-6f,
    1.5229979744712628e-8f,  1.1448674228326431e-11f
};
// w_im[k] = exp(-0.5 k^2) * sin(2 pi k / 6)  (fallback interleaved mode only)
__device__ __constant__ float c_wi[CWT_K] = {
    0.0f,                    0.5252752119703823f,    0.11720384084196092f,
    0.0f,                   -2.9051333293715680e-4f,-3.2275577425105797e-6f,
    0.0f,                    1.9829730867107332e-11f
};

template <int MODE>  // 0: real-only floats; 1: interleaved re/im floats
__global__ void __launch_bounds__(CWT_TPB)
cwt81003_kernel(const float* __restrict__ sig, float* __restrict__ out)
{
    const int t    = blockIdx.x * CWT_TPB + threadIdx.x;   // 0 .. 65535
    const int row  = t >> 9;            // (b*32 + i), 512 threads per row
    const int n0   = (t & 511) * CWT_V; // first output index in the row
    const int i    = row & (CWT_NSCALES - 1);
    const int b    = row >> 5;

    const int wl   = c_wl[i];
    const int base = n0 - wl;           // signal index of tap k=0 for output n0

    float r[CWT_V];

    if (n0 + CWT_V - 1 + CWT_K - 1 < wl) {
        // Entire 8-output window left of signal start -> zeros.
        #pragma unroll
        for (int v = 0; v < CWT_V; v++) r[v] = 0.0f;
    } else {
        float x[CWT_V + CWT_K - 1];     // 15 signal samples
        const float* p = sig + b * CWT_L + base;
        if (base >= 0) {
            #pragma unroll
            for (int j = 0; j < CWT_V + CWT_K - 1; j++) x[j] = __ldg(p + j);
        } else {
            #pragma unroll
            for (int j = 0; j < CWT_V + CWT_K - 1; j++)
                x[j] = (base + j >= 0) ? __ldg(p + j) : 0.0f;
        }
        #pragma unroll
        for (int v = 0; v < CWT_V; v++) {
            float acc = 0.0f;
            #pragma unroll
            for (int k = 0; k < CWT_K; k++)
                acc = fmaf(c_wr[k], x[v + k], acc);
            r[v] = acc;
        }
    }

    if (MODE == 0) {
        // 8 contiguous floats, 32B-aligned -> two float4 stores.
        float4* o = (float4*)(out + (long)row * CWT_L + n0);
        o[0] = make_float4(r[0], r[1], r[2], r[3]);
        o[1] = make_float4(r[4], r[5], r[6], r[7]);
    } else {
        float im[CWT_V];
        if (n0 + CWT_V - 1 + CWT_K - 1 < wl) {
            #pragma unroll
            for (int v = 0; v < CWT_V; v++) im[v] = 0.0f;
        } else {
            float x[CWT_V + CWT_K - 1];
            const float* p = sig + b * CWT_L + base;
            #pragma unroll
            for (int j = 0; j < CWT_V + CWT_K - 1; j++)
                x[j] = (base + j >= 0) ? __ldg(p + j) : 0.0f;
            #pragma unroll
            for (int v = 0; v < CWT_V; v++) {
                float acc = 0.0f;
                #pragma unroll
                for (int k = 0; k < CWT_K; k++)
                    acc = fmaf(c_wi[k], x[v + k], acc);
                im[v] = acc;
            }
        }
        float4* o = (float4*)(out + 2 * ((long)row * CWT_L + n0));
        #pragma unroll
        for (int v = 0; v < CWT_V; v += 2)
            o[v >> 1] = make_float4(r[v], im[v], r[v + 1], im[v + 1]);
    }
}

extern "C" void kernel_launch(void* const* d_in, const int* in_sizes, int n_in,
                              void* d_out, int out_size)
{
    const float* sig = (const float*)d_in[0];
    float* out = (float*)d_out;

    const long logical = (long)CWT_B * CWT_NSCALES * CWT_L;  // 524288 outputs
    const int nthreads = (int)(logical / CWT_V);             // 65536
    const int nblocks  = nthreads / CWT_TPB;                 // 256

    if ((long)out_size >= 2 * logical)
        cwt81003_kernel<1><<<nblocks, CWT_TPB>>>(sig, out);
    else
        cwt81003_kernel<0><<<nblocks, CWT_TPB>>>(sig, out);
}

// round 7
// speedup vs baseline: 1.3950x; 1.0750x over previous
#include <cuda_runtime.h>

// CWT: out[b,i,n] = Re{ sum_{k=0}^{7} w[k] * signal[b, n - wl_i + k] }
// w[k] = exp(-0.5 k^2) * exp(j*2pi*k/6), nrm = 1; envelope < 1.3e-14 past k=7.
// Output buffer = float32 real part (out_size == 524288, confirmed R5/R6).
// Latency-bound kernel: V=4 outputs/thread, 1024 CTAs x 128 -> ~27 warps/SM.

#define CWT_NSCALES 32
#define CWT_L       4096
#define CWT_B       4
#define CWT_K       8
#define CWT_V       4      // outputs per thread
#define CWT_TPB     128

__constant__ int c_wl[CWT_NSCALES] = {
      64,  194,  324,  454,  584,  714,  844,  974,
    1104, 1234, 1364, 1494, 1624, 1754, 1884, 2014,
    2048, 2048, 2048, 2048, 2048, 2048, 2048, 2048,
    2048, 2048, 2048, 2048, 2048, 2048, 2048, 2048
};

// w_re[k] = exp(-0.5 k^2) * cos(2 pi k / 6)
__device__ __constant__ float c_wr[CWT_K] = {
    1.0f,                    0.3032653298563167f,  -0.06766764161830635f,
   -0.011108996538242306f,  -1.6773131395125593e-4f, 1.8633265860393355e-6f,
    1.5229979744712628e-8f,  1.1448674228326431e-11f
};
// w_im[k] (fallback interleaved mode only)
__device__ __constant__ float c_wi[CWT_K] = {
    0.0f,                    0.5252752119703823f,    0.11720384084196092f,
    0.0f,                   -2.9051333293715680e-4f,-3.2275577425105797e-6f,
    0.0f,                    1.9829730867107332e-11f
};

template <int MODE>  // 0: real-only floats; 1: interleaved re/im floats
__global__ void __launch_bounds__(CWT_TPB)
cwt81003_kernel(const float* __restrict__ sig, float* __restrict__ out)
{
    const int t   = blockIdx.x * CWT_TPB + threadIdx.x;  // 0 .. 131071
    const int row = t >> 10;                 // (b*32 + i); 1024 threads per row
    const int n0  = (t & 1023) * CWT_V;      // first output index in the row
    const int i   = row & (CWT_NSCALES - 1);
    const int b   = row >> 5;

    const int wl   = c_wl[i];
    const int base = n0 - wl;                // signal index of tap k=0 at n0

    float r[CWT_V];

    if (n0 + CWT_V - 1 + CWT_K - 1 < wl) {
        #pragma unroll
        for (int v = 0; v < CWT_V; v++) r[v] = 0.0f;
    } else {
        float x[CWT_V + CWT_K - 1];          // 11 signal samples
        const float* p = sig + b * CWT_L + base;
        if (base >= 0) {
            #pragma unroll
            for (int j = 0; j < CWT_V + CWT_K - 1; j++) x[j] = __ldg(p + j);
        } else {
            #pragma unroll
            for (int j = 0; j < CWT_V + CWT_K - 1; j++)
                x[j] = (base + j >= 0) ? __ldg(p + j) : 0.0f;
        }
        #pragma unroll
        for (int v = 0; v < CWT_V; v++) {
            float acc = 0.0f;
            #pragma unroll
            for (int k = 0; k < CWT_K; k++)
                acc = fmaf(c_wr[k], x[v + k], acc);
            r[v] = acc;
        }
    }

    if (MODE == 0) {
        // n0 % 4 == 0 -> 16B-aligned single float4 store.
        *(float4*)(out + (long)row * CWT_L + n0) =
            make_float4(r[0], r[1], r[2], r[3]);
    } else {
        float im[CWT_V];
        if (n0 + CWT_V - 1 + CWT_K - 1 < wl) {
            #pragma unroll
            for (int v = 0; v < CWT_V; v++) im[v] = 0.0f;
        } else {
            float x[CWT_V + CWT_K - 1];
            const float* p = sig + b * CWT_L + base;
            #pragma unroll
            for (int j = 0; j < CWT_V + CWT_K - 1; j++)
                x[j] = (base + j >= 0) ? __ldg(p + j) : 0.0f;
            #pragma unroll
            for (int v = 0; v < CWT_V; v++) {
                float acc = 0.0f;
                #pragma unroll
                for (int k = 0; k < CWT_K; k++)
                    acc = fmaf(c_wi[k], x[v + k], acc);
                im[v] = acc;
            }
        }
        float4* o = (float4*)(out + 2 * ((long)row * CWT_L + n0));
        o[0] = make_float4(r[0], im[0], r[1], im[1]);
        o[1] = make_float4(r[2], im[2], r[3], im[3]);
    }
}

extern "C" void kernel_launch(void* const* d_in, const int* in_sizes, int n_in,
                              void* d_out, int out_size)
{
    const float* sig = (const float*)d_in[0];
    float* out = (float*)d_out;

    const long logical = (long)CWT_B * CWT_NSCALES * CWT_L;     // 524288 outputs
    const int nblocks  = (int)(logical / CWT_V / CWT_TPB);      // 1024

    if ((long)out_size >= 2 * logical)
        cwt81003_kernel<1><<<nblocks, CWT_TPB>>>(sig, out);
    else
        cwt81003_kernel<0><<<nblocks, CWT_TPB>>>(sig, out);
}

// round 8
// speedup vs baseline: 1.6034x; 1.1494x over previous
#include <cuda_runtime.h>

// CWT: out[b,i,n] = Re{ sum_{k=0}^{5} w[k] * signal[b, n - wl_i + k] }
// w[k] = exp(-0.5 k^2) * exp(j*2pi*k/6), nrm=1. Taps k>=6 are < 1.6e-8 and
// k=5 ~ 1.9e-6: truncating at K=6 keeps rel_err ~2e-6 (threshold 1e-3).
// Output buffer = float32 real part (out_size == 524288, confirmed R5-R7).
// V=2 outputs/thread, aligned float2 loads (wl and n0 both even -> base even).

#define CWT_NSCALES 32
#define CWT_L       4096
#define CWT_B       4
#define CWT_K       6
#define CWT_V       2
#define CWT_TPB     256

__constant__ int c_wl[CWT_NSCALES] = {
      64,  194,  324,  454,  584,  714,  844,  974,
    1104, 1234, 1364, 1494, 1624, 1754, 1884, 2014,
    2048, 2048, 2048, 2048, 2048, 2048, 2048, 2048,
    2048, 2048, 2048, 2048, 2048, 2048, 2048, 2048
};

// w_re[k] = exp(-0.5 k^2) * cos(2 pi k / 6)
__device__ __constant__ float c_wr[CWT_K] = {
    1.0f,                   0.3032653298563167f,   -0.06766764161830635f,
   -0.011108996538242306f, -1.6773131395125593e-4f, 1.8633265860393355e-6f
};
// w_im[k] (fallback interleaved mode only)
__device__ __constant__ float c_wi[CWT_K] = {
    0.0f,                   0.5252752119703823f,     0.11720384084196092f,
    0.0f,                  -2.9051333293715680e-4f, -3.2275577425105797e-6f
};

template <int MODE>  // 0: real-only floats; 1: interleaved re/im floats
__global__ void __launch_bounds__(CWT_TPB)
cwt81003_kernel(const float* __restrict__ sig, float* __restrict__ out)
{
    const int t   = blockIdx.x * CWT_TPB + threadIdx.x;  // 0 .. 262143
    const int row = t >> 11;                  // (b*32+i); 2048 threads per row
    const int n0  = (t & 2047) * CWT_V;       // even
    const int i   = row & (CWT_NSCALES - 1);
    const int b   = row >> 5;

    const int wl   = c_wl[i];
    const int base = n0 - wl;                 // even

    float r0 = 0.0f, r1 = 0.0f;
    float i0 = 0.0f, i1 = 0.0f;

    if (n0 + CWT_V - 1 + CWT_K - 1 >= wl) {   // window touches the signal
        float x[CWT_V + CWT_K - 1];           // 7 samples
        const float* p = sig + b * CWT_L + base;
        if (base >= 0) {
            // base even, sig 8B-aligned -> four aligned float2 loads (8 floats, 7 used)
            const float2* p2 = (const float2*)p;
            float2 a = __ldg(p2 + 0);
            float2 c = __ldg(p2 + 1);
            float2 d = __ldg(p2 + 2);
            float2 e = __ldg(p2 + 3);
            x[0] = a.x; x[1] = a.y; x[2] = c.x; x[3] = c.y;
            x[4] = d.x; x[5] = d.y; x[6] = e.x;
        } else {
            #pragma unroll
            for (int j = 0; j < CWT_V + CWT_K - 1; j++)
                x[j] = (base + j >= 0) ? __ldg(p + j) : 0.0f;
        }
        #pragma unroll
        for (int k = 0; k < CWT_K; k++) {
            r0 = fmaf(c_wr[k], x[k],     r0);
            r1 = fmaf(c_wr[k], x[k + 1], r1);
            if (MODE == 1) {
                i0 = fmaf(c_wi[k], x[k],     i0);
                i1 = fmaf(c_wi[k], x[k + 1], i1);
            }
        }
    }

    if (MODE == 0) {
        *(float2*)(out + (long)row * CWT_L + n0) = make_float2(r0, r1);
    } else {
        *(float4*)(out + 2 * ((long)row * CWT_L + n0)) = make_float4(r0, i0, r1, i1);
    }
}

extern "C" void kernel_launch(void* const* d_in, const int* in_sizes, int n_in,
                              void* d_out, int out_size)
{
    const float* sig = (const float*)d_in[0];
    float* out = (float*)d_out;

    const long logical = (long)CWT_B * CWT_NSCALES * CWT_L;   // 524288 outputs
    const int nblocks  = (int)(logical / CWT_V / CWT_TPB);    // 1024

    if ((long)out_size >= 2 * logical)
        cwt81003_kernel<1><<<nblocks, CWT_TPB>>>(sig, out);
    else
        cwt81003_kernel<0><<<nblocks, CWT_TPB>>>(sig, out);
}